// round 2
// baseline (speedup 1.0000x reference)
#include <cuda_runtime.h>

#define NMAX 100000
#define EMAX 1600000
#define HD 64

// Scratch (device globals — allocation-free per harness rules)
__device__ float g_deg[NMAX];          // degree, then dinv (in place)
__device__ float g_hw [NMAX * HD];     // h @ W (per layer, reused)
__device__ float g_h1 [NMAX * HD];     // post-relu layer-1 output
__device__ float g_acc1[NMAX * HD];    // scatter accumulator layer 1
__device__ float g_acc2[NMAX * HD];    // scatter accumulator layer 2
__device__ float g_pool[HD];           // feature sums for mean pool

// ---------------------------------------------------------------------------
// init: zero accumulators + pool (float4 stores), deg = 1.0 (self-loop weight)
__global__ void k_init(int n) {
    int i = blockIdx.x * blockDim.x + threadIdx.x;
    int stride = gridDim.x * blockDim.x;
    int tot4 = n * 16;                       // n*64 floats = n*16 float4
    float4 z = make_float4(0.f, 0.f, 0.f, 0.f);
    float4* a1 = (float4*)g_acc1;
    float4* a2 = (float4*)g_acc2;
    for (int j = i; j < tot4; j += stride) { a1[j] = z; a2[j] = z; }
    for (int j = i; j < n;    j += stride) g_deg[j] = 1.0f;
    if (i < HD) g_pool[i] = 0.f;
}

// deg[row[e]] += attr[e]
__global__ void k_deg(const int* __restrict__ rowp, const float* __restrict__ attr, int e) {
    int i = blockIdx.x * blockDim.x + threadIdx.x;
    if (i < e) atomicAdd(&g_deg[rowp[i]], attr[i]);
}

// dinv = rsqrt(deg)  (deg >= 1 always)
__global__ void k_dinv(int n) {
    int i = blockIdx.x * blockDim.x + threadIdx.x;
    if (i < n) g_deg[i] = rsqrtf(g_deg[i]);
}

// ---------------------------------------------------------------------------
// GEMM v3: g_hw = in @ W   (in: [n,64], W: [64,64])
// 256 threads, 128 rows/block. Thread computes 2 rows x 16 cols (32 acc regs).
// W staged in shared (16KB); X rows streamed from global (L1-resident, 4x
// c-group reuse). sW bank conflict (c0 0 vs 32) removed via q-order swizzle.
__global__ void __launch_bounds__(256) k_gemm(const float* __restrict__ inp,
                                              const float* __restrict__ W,
                                              int use_h1, int n) {
    __shared__ float sW[64 * 64];
    const float* in = use_h1 ? g_h1 : inp;
    int tid = threadIdx.x;
    for (int j = tid; j < 1024; j += 256)
        ((float4*)sW)[j] = ((const float4*)W)[j];
    __syncthreads();

    int c0  = (tid & 3) * 16;
    int swz = (tid & 2) ? 2 : 0;           // q-order swizzle: kills 2-way conflict
    int r0  = blockIdx.x * 128 + (tid >> 2) * 2;
    bool v0 = (r0 < n), v1 = (r0 + 1 < n);
    const float* rowA = in + (size_t)r0 * 64;
    const float* rowB = rowA + 64;

    float accA[16], accB[16];
#pragma unroll
    for (int q = 0; q < 16; q++) { accA[q] = 0.f; accB[q] = 0.f; }

#pragma unroll
    for (int k4 = 0; k4 < 64; k4 += 4) {
        float4 xa = v0 ? *(const float4*)(rowA + k4) : make_float4(0.f, 0.f, 0.f, 0.f);
        float4 xb = v1 ? *(const float4*)(rowB + k4) : make_float4(0.f, 0.f, 0.f, 0.f);
        float xs_a[4] = {xa.x, xa.y, xa.z, xa.w};
        float xs_b[4] = {xb.x, xb.y, xb.z, xb.w};
#pragma unroll
        for (int kk = 0; kk < 4; kk++) {
            int k = k4 + kk;
#pragma unroll
            for (int i = 0; i < 4; i++) {
                int q = i ^ swz;
                float4 w = *(const float4*)&sW[k * 64 + c0 + q * 4];
                accA[q * 4 + 0] += xs_a[kk] * w.x;
                accA[q * 4 + 1] += xs_a[kk] * w.y;
                accA[q * 4 + 2] += xs_a[kk] * w.z;
                accA[q * 4 + 3] += xs_a[kk] * w.w;
                accB[q * 4 + 0] += xs_b[kk] * w.x;
                accB[q * 4 + 1] += xs_b[kk] * w.y;
                accB[q * 4 + 2] += xs_b[kk] * w.z;
                accB[q * 4 + 3] += xs_b[kk] * w.w;
            }
        }
    }

    if (v0) {
        float* dst = &g_hw[(size_t)r0 * 64 + c0];
#pragma unroll
        for (int q = 0; q < 4; q++)
            *(float4*)(dst + q * 4) = make_float4(accA[q * 4], accA[q * 4 + 1],
                                                  accA[q * 4 + 2], accA[q * 4 + 3]);
    }
    if (v1) {
        float* dst = &g_hw[(size_t)(r0 + 1) * 64 + c0];
#pragma unroll
        for (int q = 0; q < 4; q++)
            *(float4*)(dst + q * 4) = make_float4(accB[q * 4], accB[q * 4 + 1],
                                                  accB[q * 4 + 2], accB[q * 4 + 3]);
    }
}

// ---------------------------------------------------------------------------
// Edge scatter: acc[row] += norm * hw[col]   (norm = dinv[row]*attr*dinv[col])
// 64 edges per block; 16 threads per edge, float4 per thread; vector red.
#define EPB 64
__global__ void k_scatter(const int* __restrict__ rowp, const int* __restrict__ colp,
                          const float* __restrict__ attr, int which, int e) {
    __shared__ int   s_row[EPB];
    __shared__ int   s_col[EPB];
    __shared__ float s_nrm[EPB];
    float* acc = which ? g_acc2 : g_acc1;
    int tid = threadIdx.x;
    int base = blockIdx.x * EPB;
    if (tid < EPB) {
        int ei = base + tid;
        if (ei < e) {
            int r = rowp[ei], c = colp[ei];
            s_row[tid] = r;
            s_col[tid] = c;
            s_nrm[tid] = g_deg[r] * attr[ei] * g_deg[c];
        } else {
            s_row[tid] = -1;
        }
    }
    __syncthreads();
    int g = tid >> 4, t = tid & 15;
#pragma unroll
    for (int it = 0; it < 4; it++) {
        int li = g + it * 16;
        int r = s_row[li];
        if (r < 0) continue;
        float nrm = s_nrm[li];
        const float4 v = *(const float4*)&g_hw[(size_t)s_col[li] * 64 + t * 4];
        float* dst = &acc[(size_t)r * 64 + t * 4];
        asm volatile("red.global.add.v4.f32 [%0], {%1,%2,%3,%4};"
                     :: "l"(dst), "f"(v.x * nrm), "f"(v.y * nrm),
                        "f"(v.z * nrm), "f"(v.w * nrm)
                     : "memory");
    }
}

// ---------------------------------------------------------------------------
// layer-1 epilogue: h1 = relu(acc1 + dinv^2 * hw + b1)
__global__ void k_post1(const float* __restrict__ bias, int n) {
    int idx = blockIdx.x * blockDim.x + threadIdx.x;  // one float4 per thread
    if (idx >= n * 16) return;
    int i = idx >> 4, q = idx & 15;
    float d = g_deg[i];
    float sl = d * d;
    float4 a  = *(const float4*)&g_acc1[(size_t)idx * 4];
    float4 hv = *(const float4*)&g_hw [(size_t)idx * 4];
    float4 b  = *(const float4*)&bias[q * 4];
    float4 r;
    r.x = fmaxf(a.x + sl * hv.x + b.x, 0.f);
    r.y = fmaxf(a.y + sl * hv.y + b.y, 0.f);
    r.z = fmaxf(a.z + sl * hv.z + b.z, 0.f);
    r.w = fmaxf(a.w + sl * hv.w + b.w, 0.f);
    *(float4*)&g_h1[(size_t)idx * 4] = r;
}

// layer-2 epilogue fused with mean-pool accumulation
__global__ void k_post2_pool(const float* __restrict__ bias, int n) {
    __shared__ float4 sbuf[256];
    int tid = threadIdx.x;
    int q = tid & 15, r = tid >> 4;
    float4 b = *(const float4*)&bias[q * 4];
    float4 sum = make_float4(0.f, 0.f, 0.f, 0.f);
    int base = blockIdx.x * 1024;
#pragma unroll 4
    for (int it = 0; it < 64; it++) {
        int i = base + r + (it << 4);
        if (i >= n) break;
        float d = g_deg[i];
        float sl = d * d;
        const float4 a  = *(const float4*)&g_acc2[(size_t)i * 64 + q * 4];
        const float4 hv = *(const float4*)&g_hw [(size_t)i * 64 + q * 4];
        sum.x += fmaxf(a.x + sl * hv.x + b.x, 0.f);
        sum.y += fmaxf(a.y + sl * hv.y + b.y, 0.f);
        sum.z += fmaxf(a.z + sl * hv.z + b.z, 0.f);
        sum.w += fmaxf(a.w + sl * hv.w + b.w, 0.f);
    }
    sbuf[tid] = sum;
    __syncthreads();
    if (r == 0) {
        float4 tot = sbuf[q];
#pragma unroll
        for (int j = 1; j < 16; j++) {
            float4 v = sbuf[q + 16 * j];
            tot.x += v.x; tot.y += v.y; tot.z += v.z; tot.w += v.w;
        }
        float* dst = &g_pool[q * 4];
        asm volatile("red.global.add.v4.f32 [%0], {%1,%2,%3,%4};"
                     :: "l"(dst), "f"(tot.x), "f"(tot.y), "f"(tot.z), "f"(tot.w)
                     : "memory");
    }
}

// ---------------------------------------------------------------------------
// head: z = [pool/n, h_other];  out = relu(z@Wc1+bc1) @ Wc2 + bc2
__global__ void k_head(const float* __restrict__ Wc1, const float* __restrict__ bc1,
                       const float* __restrict__ Wc2, const float* __restrict__ bc2,
                       const float* __restrict__ h_other, float* __restrict__ out, int n) {
    __shared__ float z[128];
    __shared__ float hid[64];
    int t = threadIdx.x;
    if (t < 64) {
        z[t]      = g_pool[t] / (float)n;
        z[64 + t] = h_other[t];
    }
    __syncthreads();
    if (t < 64) {
        float s = bc1[t];
#pragma unroll 8
        for (int i = 0; i < 128; i++) s += z[i] * Wc1[i * 64 + t];
        hid[t] = fmaxf(s, 0.f);
    }
    __syncthreads();
    if (t < 3) {
        float s = bc2[t];
#pragma unroll
        for (int j = 0; j < 64; j++) s += hid[j] * Wc2[j * 3 + t];
        out[t] = s;
    }
}

// ---------------------------------------------------------------------------
extern "C" void kernel_launch(void* const* d_in, const int* in_sizes, int n_in,
                              void* d_out, int out_size) {
    const float* x        = (const float*)d_in[0];
    const int*   eidx     = (const int*)  d_in[1];
    const float* eattr    = (const float*)d_in[2];
    // d_in[3] = batch (unused; single graph)
    const float* W1       = (const float*)d_in[4];
    const float* b1       = (const float*)d_in[5];
    const float* W2       = (const float*)d_in[6];
    const float* b2       = (const float*)d_in[7];
    const float* Wc1      = (const float*)d_in[8];
    const float* bc1      = (const float*)d_in[9];
    const float* Wc2      = (const float*)d_in[10];
    const float* bc2      = (const float*)d_in[11];
    const float* h_other  = (const float*)d_in[12];
    float* out = (float*)d_out;

    int n = in_sizes[0] / HD;      // nodes
    int e = in_sizes[2];           // edges
    const int* rowp = eidx;
    const int* colp = eidx + e;

    // 1) init scratch
    k_init<<<2048, 256>>>(n);
    // 2) degree + dinv
    k_deg<<<(e + 255) / 256, 256>>>(rowp, eattr, e);
    k_dinv<<<(n + 255) / 256, 256>>>(n);
    // 3) layer 1: gemm -> scatter -> relu
    k_gemm<<<(n + 127) / 128, 256>>>(x, W1, 0, n);
    k_scatter<<<(e + EPB - 1) / EPB, 256>>>(rowp, colp, eattr, 0, e);
    k_post1<<<(n * 16 + 255) / 256, 256>>>(b1, n);
    // 4) layer 2: gemm -> scatter -> relu + pool
    k_gemm<<<(n + 127) / 128, 256>>>(x, W2, 1, n);
    k_scatter<<<(e + EPB - 1) / EPB, 256>>>(rowp, colp, eattr, 1, e);
    k_post2_pool<<<(n + 1023) / 1024, 256>>>(b2, n);
    // 5) head
    k_head<<<1, 64>>>(Wc1, bc1, Wc2, bc2, h_other, out, n);
}

// round 3
// speedup vs baseline: 3.9712x; 3.9712x over previous
#include <cuda_runtime.h>

#define NMAX 100000
#define EMAX 1600000
#define HD 64

// Scratch (device globals — allocation-free per harness rules)
__device__ float g_deg[NMAX];          // degree, then dinv (in place)
__device__ float g_hw [NMAX * HD];     // h @ W (per layer, reused)
__device__ float g_h1 [NMAX * HD];     // post-relu layer-1 output
__device__ float g_acc1[NMAX * HD];    // scatter accumulator layer 1
__device__ float g_acc2[NMAX * HD];    // scatter accumulator layer 2
__device__ float g_pool[HD];           // feature sums for mean pool

// ---------------------------------------------------------------------------
// init: zero accumulators + pool (float4 stores), deg = 1.0 (self-loop weight)
__global__ void k_init(int n) {
    int i = blockIdx.x * blockDim.x + threadIdx.x;
    int stride = gridDim.x * blockDim.x;
    int tot4 = n * 16;                       // n*64 floats = n*16 float4
    float4 z = make_float4(0.f, 0.f, 0.f, 0.f);
    float4* a1 = (float4*)g_acc1;
    float4* a2 = (float4*)g_acc2;
    for (int j = i; j < tot4; j += stride) { a1[j] = z; a2[j] = z; }
    for (int j = i; j < n;    j += stride) g_deg[j] = 1.0f;
    if (i < HD) g_pool[i] = 0.f;
}

// deg[row[e]] += attr[e]
__global__ void k_deg(const int* __restrict__ rowp, const float* __restrict__ attr, int e) {
    int i = blockIdx.x * blockDim.x + threadIdx.x;
    if (i < e) atomicAdd(&g_deg[rowp[i]], attr[i]);
}

// dinv = rsqrt(deg)  (deg >= 1 always)
__global__ void k_dinv(int n) {
    int i = blockIdx.x * blockDim.x + threadIdx.x;
    if (i < n) g_deg[i] = rsqrtf(g_deg[i]);
}

// ---------------------------------------------------------------------------
// GEMM v4: g_hw = in @ W   (in: [n,64], W: [64,64])
// 256 threads, 128 rows/block. Thread computes 2 rows x 16 cols.
// All accumulator indices are STATIC (literal unroll) — no local-mem demotion.
// W staged in shared; X rows streamed from global (L1-resident, warp-broadcast).
__global__ void __launch_bounds__(256) k_gemm(const float* __restrict__ inp,
                                              const float* __restrict__ W,
                                              int use_h1, int n) {
    __shared__ float sW[64 * 64];
    const float* in = use_h1 ? g_h1 : inp;
    int tid = threadIdx.x;
    for (int j = tid; j < 1024; j += 256)
        ((float4*)sW)[j] = ((const float4*)W)[j];
    __syncthreads();

    int c0 = (tid & 3) * 16;
    int r0 = blockIdx.x * 128 + (tid >> 2) * 2;
    bool v0 = (r0 < n), v1 = (r0 + 1 < n);
    const float* rowA = in + (size_t)r0 * 64;
    const float* rowB = rowA + 64;

    float4 accA[4], accB[4];
#pragma unroll
    for (int q = 0; q < 4; q++) {
        accA[q] = make_float4(0.f, 0.f, 0.f, 0.f);
        accB[q] = make_float4(0.f, 0.f, 0.f, 0.f);
    }

#pragma unroll
    for (int k4 = 0; k4 < 64; k4 += 4) {
        float4 xa = v0 ? *(const float4*)(rowA + k4) : make_float4(0.f, 0.f, 0.f, 0.f);
        float4 xb = v1 ? *(const float4*)(rowB + k4) : make_float4(0.f, 0.f, 0.f, 0.f);
        float xs_a[4] = {xa.x, xa.y, xa.z, xa.w};
        float xs_b[4] = {xb.x, xb.y, xb.z, xb.w};
#pragma unroll
        for (int kk = 0; kk < 4; kk++) {
            int k = k4 + kk;
            float a = xs_a[kk], b = xs_b[kk];
#pragma unroll
            for (int q = 0; q < 4; q++) {
                float4 w = *(const float4*)&sW[k * 64 + c0 + q * 4];
                accA[q].x += a * w.x;  accA[q].y += a * w.y;
                accA[q].z += a * w.z;  accA[q].w += a * w.w;
                accB[q].x += b * w.x;  accB[q].y += b * w.y;
                accB[q].z += b * w.z;  accB[q].w += b * w.w;
            }
        }
    }

    if (v0) {
        float* dst = &g_hw[(size_t)r0 * 64 + c0];
#pragma unroll
        for (int q = 0; q < 4; q++) *(float4*)(dst + q * 4) = accA[q];
    }
    if (v1) {
        float* dst = &g_hw[(size_t)(r0 + 1) * 64 + c0];
#pragma unroll
        for (int q = 0; q < 4; q++) *(float4*)(dst + q * 4) = accB[q];
    }
}

// ---------------------------------------------------------------------------
// Edge scatter: acc[row] += norm * hw[col]   (norm = dinv[row]*attr*dinv[col])
// 64 edges per block; 16 threads per edge, float4 per thread; vector red.
#define EPB 64
__global__ void k_scatter(const int* __restrict__ rowp, const int* __restrict__ colp,
                          const float* __restrict__ attr, int which, int e) {
    __shared__ int   s_row[EPB];
    __shared__ int   s_col[EPB];
    __shared__ float s_nrm[EPB];
    float* acc = which ? g_acc2 : g_acc1;
    int tid = threadIdx.x;
    int base = blockIdx.x * EPB;
    if (tid < EPB) {
        int ei = base + tid;
        if (ei < e) {
            int r = rowp[ei], c = colp[ei];
            s_row[tid] = r;
            s_col[tid] = c;
            s_nrm[tid] = g_deg[r] * attr[ei] * g_deg[c];
        } else {
            s_row[tid] = -1;
        }
    }
    __syncthreads();
    int g = tid >> 4, t = tid & 15;
#pragma unroll
    for (int it = 0; it < 4; it++) {
        int li = g + it * 16;
        int r = s_row[li];
        if (r < 0) continue;
        float nrm = s_nrm[li];
        const float4 v = *(const float4*)&g_hw[(size_t)s_col[li] * 64 + t * 4];
        float* dst = &acc[(size_t)r * 64 + t * 4];
        asm volatile("red.global.add.v4.f32 [%0], {%1,%2,%3,%4};"
                     :: "l"(dst), "f"(v.x * nrm), "f"(v.y * nrm),
                        "f"(v.z * nrm), "f"(v.w * nrm)
                     : "memory");
    }
}

// ---------------------------------------------------------------------------
// layer-1 epilogue: h1 = relu(acc1 + dinv^2 * hw + b1)
__global__ void k_post1(const float* __restrict__ bias, int n) {
    int idx = blockIdx.x * blockDim.x + threadIdx.x;  // one float4 per thread
    if (idx >= n * 16) return;
    int i = idx >> 4, q = idx & 15;
    float d = g_deg[i];
    float sl = d * d;
    float4 a  = *(const float4*)&g_acc1[(size_t)idx * 4];
    float4 hv = *(const float4*)&g_hw [(size_t)idx * 4];
    float4 b  = *(const float4*)&bias[q * 4];
    float4 r;
    r.x = fmaxf(a.x + sl * hv.x + b.x, 0.f);
    r.y = fmaxf(a.y + sl * hv.y + b.y, 0.f);
    r.z = fmaxf(a.z + sl * hv.z + b.z, 0.f);
    r.w = fmaxf(a.w + sl * hv.w + b.w, 0.f);
    *(float4*)&g_h1[(size_t)idx * 4] = r;
}

// layer-2 epilogue fused with mean-pool accumulation
__global__ void k_post2_pool(const float* __restrict__ bias, int n) {
    __shared__ float4 sbuf[256];
    int tid = threadIdx.x;
    int q = tid & 15, r = tid >> 4;
    float4 b = *(const float4*)&bias[q * 4];
    float4 sum = make_float4(0.f, 0.f, 0.f, 0.f);
    int base = blockIdx.x * 1024;
#pragma unroll 4
    for (int it = 0; it < 64; it++) {
        int i = base + r + (it << 4);
        if (i >= n) break;
        float d = g_deg[i];
        float sl = d * d;
        const float4 a  = *(const float4*)&g_acc2[(size_t)i * 64 + q * 4];
        const float4 hv = *(const float4*)&g_hw [(size_t)i * 64 + q * 4];
        sum.x += fmaxf(a.x + sl * hv.x + b.x, 0.f);
        sum.y += fmaxf(a.y + sl * hv.y + b.y, 0.f);
        sum.z += fmaxf(a.z + sl * hv.z + b.z, 0.f);
        sum.w += fmaxf(a.w + sl * hv.w + b.w, 0.f);
    }
    sbuf[tid] = sum;
    __syncthreads();
    if (r == 0) {
        float4 tot = sbuf[q];
#pragma unroll
        for (int j = 1; j < 16; j++) {
            float4 v = sbuf[q + 16 * j];
            tot.x += v.x; tot.y += v.y; tot.z += v.z; tot.w += v.w;
        }
        float* dst = &g_pool[q * 4];
        asm volatile("red.global.add.v4.f32 [%0], {%1,%2,%3,%4};"
                     :: "l"(dst), "f"(tot.x), "f"(tot.y), "f"(tot.z), "f"(tot.w)
                     : "memory");
    }
}

// ---------------------------------------------------------------------------
// head: z = [pool/n, h_other];  out = relu(z@Wc1+bc1) @ Wc2 + bc2
__global__ void k_head(const float* __restrict__ Wc1, const float* __restrict__ bc1,
                       const float* __restrict__ Wc2, const float* __restrict__ bc2,
                       const float* __restrict__ h_other, float* __restrict__ out, int n) {
    __shared__ float z[128];
    __shared__ float hid[64];
    int t = threadIdx.x;
    if (t < 64) {
        z[t]      = g_pool[t] / (float)n;
        z[64 + t] = h_other[t];
    }
    __syncthreads();
    if (t < 64) {
        float s = bc1[t];
#pragma unroll 8
        for (int i = 0; i < 128; i++) s += z[i] * Wc1[i * 64 + t];
        hid[t] = fmaxf(s, 0.f);
    }
    __syncthreads();
    if (t < 3) {
        float s = bc2[t];
#pragma unroll
        for (int j = 0; j < 64; j++) s += hid[j] * Wc2[j * 3 + t];
        out[t] = s;
    }
}

// ---------------------------------------------------------------------------
extern "C" void kernel_launch(void* const* d_in, const int* in_sizes, int n_in,
                              void* d_out, int out_size) {
    const float* x        = (const float*)d_in[0];
    const int*   eidx     = (const int*)  d_in[1];
    const float* eattr    = (const float*)d_in[2];
    // d_in[3] = batch (unused; single graph)
    const float* W1       = (const float*)d_in[4];
    const float* b1       = (const float*)d_in[5];
    const float* W2       = (const float*)d_in[6];
    const float* b2       = (const float*)d_in[7];
    const float* Wc1      = (const float*)d_in[8];
    const float* bc1      = (const float*)d_in[9];
    const float* Wc2      = (const float*)d_in[10];
    const float* bc2      = (const float*)d_in[11];
    const float* h_other  = (const float*)d_in[12];
    float* out = (float*)d_out;

    int n = in_sizes[0] / HD;      // nodes
    int e = in_sizes[2];           // edges
    const int* rowp = eidx;
    const int* colp = eidx + e;

    // 1) init scratch
    k_init<<<2048, 256>>>(n);
    // 2) degree + dinv
    k_deg<<<(e + 255) / 256, 256>>>(rowp, eattr, e);
    k_dinv<<<(n + 255) / 256, 256>>>(n);
    // 3) layer 1: gemm -> scatter -> relu
    k_gemm<<<(n + 127) / 128, 256>>>(x, W1, 0, n);
    k_scatter<<<(e + EPB - 1) / EPB, 256>>>(rowp, colp, eattr, 0, e);
    k_post1<<<(n * 16 + 255) / 256, 256>>>(b1, n);
    // 4) layer 2: gemm -> scatter -> relu + pool
    k_gemm<<<(n + 127) / 128, 256>>>(x, W2, 1, n);
    k_scatter<<<(e + EPB - 1) / EPB, 256>>>(rowp, colp, eattr, 1, e);
    k_post2_pool<<<(n + 1023) / 1024, 256>>>(b2, n);
    // 5) head
    k_head<<<1, 64>>>(Wc1, bc1, Wc2, bc2, h_other, out, n);
}

// round 5
// speedup vs baseline: 4.1061x; 1.0340x over previous
#include <cuda_runtime.h>

#define NMAX 100000
#define EMAX 1600000
#define HD 64

// Scratch (device globals — allocation-free per harness rules)
__device__ float g_deg[NMAX];          // degree, then dinv (in place)
__device__ float g_hw [NMAX * HD];     // h @ W (per layer, reused)
__device__ float g_h1 [NMAX * HD];     // post-relu layer-1 output
__device__ float g_acc1[NMAX * HD];    // scatter accumulator layer 1
__device__ float g_acc2[NMAX * HD];    // scatter accumulator layer 2
__device__ float g_pool[HD];           // feature sums for mean pool

// ---------------------------------------------------------------------------
// init: zero accumulators + pool (float4 stores), deg = 1.0 (self-loop weight)
__global__ void k_init(int n) {
    int i = blockIdx.x * blockDim.x + threadIdx.x;
    int stride = gridDim.x * blockDim.x;
    int tot4 = n * 16;                       // n*64 floats = n*16 float4
    float4 z = make_float4(0.f, 0.f, 0.f, 0.f);
    float4* a1 = (float4*)g_acc1;
    float4* a2 = (float4*)g_acc2;
    for (int j = i; j < tot4; j += stride) { a1[j] = z; a2[j] = z; }
    for (int j = i; j < n;    j += stride) g_deg[j] = 1.0f;
    if (i < HD) g_pool[i] = 0.f;
}

// deg[row[e]] += attr[e]
__global__ void k_deg(const int* __restrict__ rowp, const float* __restrict__ attr, int e) {
    int i = blockIdx.x * blockDim.x + threadIdx.x;
    if (i < e) atomicAdd(&g_deg[rowp[i]], attr[i]);
}

// dinv = rsqrt(deg)  (deg >= 1 always)
__global__ void k_dinv(int n) {
    int i = blockIdx.x * blockDim.x + threadIdx.x;
    if (i < n) g_deg[i] = rsqrtf(g_deg[i]);
}

// ---------------------------------------------------------------------------
// GEMM v5: g_hw = in @ W   (in: [n,64], W: [64,64])
// 256 threads, 128 rows/block, thread = 2 rows x 16 cols (static reg indices).
// X tile staged in shared via coalesced float4 loads (pad 65 kills bank
// conflicts on the scalar reads); W in shared (float4 broadcast reads).
// Per warp per k: 2 LDS + 4 LDS.128 vs 32 FFMA -> FFMA-bound.
__global__ void __launch_bounds__(256) k_gemm(const float* __restrict__ inp,
                                              const float* __restrict__ W,
                                              int use_h1, int n) {
    __shared__ float sW[64 * 64];
    __shared__ float sX[128 * 65];
    const float* in = use_h1 ? g_h1 : inp;
    int tid = threadIdx.x;
    for (int j = tid; j < 1024; j += 256)
        ((float4*)sW)[j] = ((const float4*)W)[j];

    int rowBase = blockIdx.x * 128;
    // stage 128x64 X tile: 2048 float4, coalesced; scalar STS into padded rows
    for (int j = tid; j < 2048; j += 256) {
        int r  = j >> 4;        // 16 float4 per row
        int c4 = (j & 15) * 4;
        int gr = rowBase + r;
        float4 v = (gr < n) ? *(const float4*)(in + (size_t)gr * 64 + c4)
                            : make_float4(0.f, 0.f, 0.f, 0.f);
        float* dst = &sX[r * 65 + c4];
        dst[0] = v.x; dst[1] = v.y; dst[2] = v.z; dst[3] = v.w;
    }
    __syncthreads();

    int c0 = (tid & 3) * 16;
    int r0 = blockIdx.x * 128 + (tid >> 2) * 2;
    int offA = ((tid >> 2) * 2) * 65;
    int offB = offA + 65;

    float4 accA[4], accB[4];
#pragma unroll
    for (int q = 0; q < 4; q++) {
        accA[q] = make_float4(0.f, 0.f, 0.f, 0.f);
        accB[q] = make_float4(0.f, 0.f, 0.f, 0.f);
    }

#pragma unroll 8
    for (int k = 0; k < 64; k++) {
        float a = sX[offA + k];
        float b = sX[offB + k];
#pragma unroll
        for (int q = 0; q < 4; q++) {
            float4 w = *(const float4*)&sW[k * 64 + c0 + q * 4];
            accA[q].x += a * w.x;  accA[q].y += a * w.y;
            accA[q].z += a * w.z;  accA[q].w += a * w.w;
            accB[q].x += b * w.x;  accB[q].y += b * w.y;
            accB[q].z += b * w.z;  accB[q].w += b * w.w;
        }
    }

    if (r0 < n) {
        float* dst = &g_hw[(size_t)r0 * 64 + c0];
#pragma unroll
        for (int q = 0; q < 4; q++) *(float4*)(dst + q * 4) = accA[q];
    }
    if (r0 + 1 < n) {
        float* dst = &g_hw[(size_t)(r0 + 1) * 64 + c0];
#pragma unroll
        for (int q = 0; q < 4; q++) *(float4*)(dst + q * 4) = accB[q];
    }
}

// ---------------------------------------------------------------------------
// Edge scatter: acc[row] += norm * hw[col]   (norm = dinv[row]*attr*dinv[col])
// 64 edges per block; 16 threads per edge, float4 per thread; vector red.
#define EPB 64
__global__ void k_scatter(const int* __restrict__ rowp, const int* __restrict__ colp,
                          const float* __restrict__ attr, int which, int e) {
    __shared__ int   s_row[EPB];
    __shared__ int   s_col[EPB];
    __shared__ float s_nrm[EPB];
    float* acc = which ? g_acc2 : g_acc1;
    int tid = threadIdx.x;
    int base = blockIdx.x * EPB;
    if (tid < EPB) {
        int ei = base + tid;
        if (ei < e) {
            int r = rowp[ei], c = colp[ei];
            s_row[tid] = r;
            s_col[tid] = c;
            s_nrm[tid] = g_deg[r] * attr[ei] * g_deg[c];
        } else {
            s_row[tid] = -1;
        }
    }
    __syncthreads();
    int g = tid >> 4, t = tid & 15;
#pragma unroll
    for (int it = 0; it < 4; it++) {
        int li = g + it * 16;
        int r = s_row[li];
        if (r < 0) continue;
        float nrm = s_nrm[li];
        const float4 v = *(const float4*)&g_hw[(size_t)s_col[li] * 64 + t * 4];
        float* dst = &acc[(size_t)r * 64 + t * 4];
        asm volatile("red.global.add.v4.f32 [%0], {%1,%2,%3,%4};"
                     :: "l"(dst), "f"(v.x * nrm), "f"(v.y * nrm),
                        "f"(v.z * nrm), "f"(v.w * nrm)
                     : "memory");
    }
}

// ---------------------------------------------------------------------------
// layer-1 epilogue: h1 = relu(acc1 + dinv^2 * hw + b1)
__global__ void k_post1(const float* __restrict__ bias, int n) {
    int idx = blockIdx.x * blockDim.x + threadIdx.x;  // one float4 per thread
    if (idx >= n * 16) return;
    int i = idx >> 4, q = idx & 15;
    float d = g_deg[i];
    float sl = d * d;
    float4 a  = *(const float4*)&g_acc1[(size_t)idx * 4];
    float4 hv = *(const float4*)&g_hw [(size_t)idx * 4];
    float4 b  = *(const float4*)&bias[q * 4];
    float4 r;
    r.x = fmaxf(a.x + sl * hv.x + b.x, 0.f);
    r.y = fmaxf(a.y + sl * hv.y + b.y, 0.f);
    r.z = fmaxf(a.z + sl * hv.z + b.z, 0.f);
    r.w = fmaxf(a.w + sl * hv.w + b.w, 0.f);
    *(float4*)&g_h1[(size_t)idx * 4] = r;
}

// layer-2 epilogue fused with mean-pool accumulation
__global__ void k_post2_pool(const float* __restrict__ bias, int n) {
    __shared__ float4 sbuf[256];
    int tid = threadIdx.x;
    int q = tid & 15, r = tid >> 4;
    float4 b = *(const float4*)&bias[q * 4];
    float4 sum = make_float4(0.f, 0.f, 0.f, 0.f);
    int base = blockIdx.x * 1024;
#pragma unroll 4
    for (int it = 0; it < 64; it++) {
        int i = base + r + (it << 4);
        if (i >= n) break;
        float d = g_deg[i];
        float sl = d * d;
        const float4 a  = *(const float4*)&g_acc2[(size_t)i * 64 + q * 4];
        const float4 hv = *(const float4*)&g_hw [(size_t)i * 64 + q * 4];
        sum.x += fmaxf(a.x + sl * hv.x + b.x, 0.f);
        sum.y += fmaxf(a.y + sl * hv.y + b.y, 0.f);
        sum.z += fmaxf(a.z + sl * hv.z + b.z, 0.f);
        sum.w += fmaxf(a.w + sl * hv.w + b.w, 0.f);
    }
    sbuf[tid] = sum;
    __syncthreads();
    if (r == 0) {
        float4 tot = sbuf[q];
#pragma unroll
        for (int j = 1; j < 16; j++) {
            float4 v = sbuf[q + 16 * j];
            tot.x += v.x; tot.y += v.y; tot.z += v.z; tot.w += v.w;
        }
        float* dst = &g_pool[q * 4];
        asm volatile("red.global.add.v4.f32 [%0], {%1,%2,%3,%4};"
                     :: "l"(dst), "f"(tot.x), "f"(tot.y), "f"(tot.z), "f"(tot.w)
                     : "memory");
    }
}

// ---------------------------------------------------------------------------
// head: z = [pool/n, h_other];  out = relu(z@Wc1+bc1) @ Wc2 + bc2
__global__ void k_head(const float* __restrict__ Wc1, const float* __restrict__ bc1,
                       const float* __restrict__ Wc2, const float* __restrict__ bc2,
                       const float* __restrict__ h_other, float* __restrict__ out, int n) {
    __shared__ float z[128];
    __shared__ float hid[64];
    int t = threadIdx.x;
    if (t < 64) {
        z[t]      = g_pool[t] / (float)n;
        z[64 + t] = h_other[t];
    }
    __syncthreads();
    if (t < 64) {
        float s = bc1[t];
#pragma unroll 8
        for (int i = 0; i < 128; i++) s += z[i] * Wc1[i * 64 + t];
        hid[t] = fmaxf(s, 0.f);
    }
    __syncthreads();
    if (t < 3) {
        float s = bc2[t];
#pragma unroll
        for (int j = 0; j < 64; j++) s += hid[j] * Wc2[j * 3 + t];
        out[t] = s;
    }
}

// ---------------------------------------------------------------------------
extern "C" void kernel_launch(void* const* d_in, const int* in_sizes, int n_in,
                              void* d_out, int out_size) {
    const float* x        = (const float*)d_in[0];
    const int*   eidx     = (const int*)  d_in[1];
    const float* eattr    = (const float*)d_in[2];
    // d_in[3] = batch (unused; single graph)
    const float* W1       = (const float*)d_in[4];
    const float* b1       = (const float*)d_in[5];
    const float* W2       = (const float*)d_in[6];
    const float* b2       = (const float*)d_in[7];
    const float* Wc1      = (const float*)d_in[8];
    const float* bc1      = (const float*)d_in[9];
    const float* Wc2      = (const float*)d_in[10];
    const float* bc2      = (const float*)d_in[11];
    const float* h_other  = (const float*)d_in[12];
    float* out = (float*)d_out;

    int n = in_sizes[0] / HD;      // nodes
    int e = in_sizes[2];           // edges
    const int* rowp = eidx;
    const int* colp = eidx + e;

    // 1) init scratch
    k_init<<<2048, 256>>>(n);
    // 2) degree + dinv
    k_deg<<<(e + 255) / 256, 256>>>(rowp, eattr, e);
    k_dinv<<<(n + 255) / 256, 256>>>(n);
    // 3) layer 1: gemm -> scatter -> relu
    k_gemm<<<(n + 127) / 128, 256>>>(x, W1, 0, n);
    k_scatter<<<(e + EPB - 1) / EPB, 256>>>(rowp, colp, eattr, 0, e);
    k_post1<<<(n * 16 + 255) / 256, 256>>>(b1, n);
    // 4) layer 2: gemm -> scatter -> relu + pool
    k_gemm<<<(n + 127) / 128, 256>>>(x, W2, 1, n);
    k_scatter<<<(e + EPB - 1) / EPB, 256>>>(rowp, colp, eattr, 1, e);
    k_post2_pool<<<(n + 1023) / 1024, 256>>>(b2, n);
    // 5) head
    k_head<<<1, 64>>>(Wc1, bc1, Wc2, bc2, h_other, out, n);
}

// round 6
// speedup vs baseline: 4.7370x; 1.1536x over previous
#include <cuda_runtime.h>
#include <cuda_fp16.h>

#define NMAX 100000
#define EMAX 1600000
#define HD 64

// Scratch (device globals — allocation-free per harness rules)
__device__ float  g_deg[NMAX];          // degree, then dinv (in place)
__device__ float  g_hw [NMAX * HD];     // h @ W (per layer, fp32)
__device__ __half g_hwh[NMAX * HD];     // h @ W (per layer, fp16 mirror for gather)
__device__ float  g_h1 [NMAX * HD];     // post-relu layer-1 output
__device__ float  g_acc1[NMAX * HD];    // scatter accumulator layer 1
__device__ float  g_acc2[NMAX * HD];    // scatter accumulator layer 2
__device__ float  g_pool[HD];           // feature sums for mean pool

// ---------------------------------------------------------------------------
// init: zero accumulators + pool (float4 stores), deg = 1.0 (self-loop weight)
__global__ void k_init(int n) {
    int i = blockIdx.x * blockDim.x + threadIdx.x;
    int stride = gridDim.x * blockDim.x;
    int tot4 = n * 16;                       // n*64 floats = n*16 float4
    float4 z = make_float4(0.f, 0.f, 0.f, 0.f);
    float4* a1 = (float4*)g_acc1;
    float4* a2 = (float4*)g_acc2;
    for (int j = i; j < tot4; j += stride) { a1[j] = z; a2[j] = z; }
    for (int j = i; j < n;    j += stride) g_deg[j] = 1.0f;
    if (i < HD) g_pool[i] = 0.f;
}

// deg[row[e]] += attr[e]
__global__ void k_deg(const int* __restrict__ rowp, const float* __restrict__ attr, int e) {
    int i = blockIdx.x * blockDim.x + threadIdx.x;
    if (i < e) atomicAdd(&g_deg[rowp[i]], attr[i]);
}

// dinv = rsqrt(deg)  (deg >= 1 always)
__global__ void k_dinv(int n) {
    int i = blockIdx.x * blockDim.x + threadIdx.x;
    if (i < n) g_deg[i] = rsqrtf(g_deg[i]);
}

// ---------------------------------------------------------------------------
// helper: pack float4 -> 4x half (uint2)
__device__ __forceinline__ uint2 pack_half4(float4 v) {
    __half2 lo = __floats2half2_rn(v.x, v.y);
    __half2 hi = __floats2half2_rn(v.z, v.w);
    uint2 u;
    u.x = *(unsigned int*)&lo;
    u.y = *(unsigned int*)&hi;
    return u;
}

// GEMM v6: g_hw(+g_hwh) = in @ W   (in: [n,64], W: [64,64])
// 256 threads, 64 rows/block. Thread = 2 rows x 8 INTERLEAVED cols:
// c = (tid&7)*4 + q*32, q in {0,1}. The 8 lane addresses of each LDS.128
// span all 32 banks -> conflict-free. Static accumulator indices.
// ~40 regs -> 4-5 blocks/SM -> FMA pipe actually fed.
__global__ void __launch_bounds__(256) k_gemm(const float* __restrict__ inp,
                                              const float* __restrict__ W,
                                              int use_h1, int n) {
    __shared__ float sW[64 * 64];
    __shared__ float sX[64 * 65];
    const float* in = use_h1 ? g_h1 : inp;
    int tid = threadIdx.x;
    for (int j = tid; j < 1024; j += 256)
        ((float4*)sW)[j] = ((const float4*)W)[j];

    int rowBase = blockIdx.x * 64;
    for (int j = tid; j < 1024; j += 256) {   // 64 rows x 16 float4
        int r  = j >> 4;
        int c4 = (j & 15) * 4;
        int gr = rowBase + r;
        float4 v = (gr < n) ? *(const float4*)(in + (size_t)gr * 64 + c4)
                            : make_float4(0.f, 0.f, 0.f, 0.f);
        float* dst = &sX[r * 65 + c4];
        dst[0] = v.x; dst[1] = v.y; dst[2] = v.z; dst[3] = v.w;
    }
    __syncthreads();

    int c0 = (tid & 7) * 4;
    int rr = (tid >> 3) * 2;
    int r0 = rowBase + rr;
    int offA = rr * 65, offB = offA + 65;

    float4 aA0 = make_float4(0.f,0.f,0.f,0.f), aA1 = aA0, aB0 = aA0, aB1 = aA0;

#pragma unroll 8
    for (int k = 0; k < 64; k++) {
        float a = sX[offA + k];
        float b = sX[offB + k];
        float4 w0 = *(const float4*)&sW[k * 64 + c0];
        float4 w1 = *(const float4*)&sW[k * 64 + 32 + c0];
        aA0.x += a * w0.x; aA0.y += a * w0.y; aA0.z += a * w0.z; aA0.w += a * w0.w;
        aA1.x += a * w1.x; aA1.y += a * w1.y; aA1.z += a * w1.z; aA1.w += a * w1.w;
        aB0.x += b * w0.x; aB0.y += b * w0.y; aB0.z += b * w0.z; aB0.w += b * w0.w;
        aB1.x += b * w1.x; aB1.y += b * w1.y; aB1.z += b * w1.z; aB1.w += b * w1.w;
    }

    if (r0 < n) {
        size_t base = (size_t)r0 * 64;
        *(float4*)&g_hw[base + c0]      = aA0;
        *(float4*)&g_hw[base + 32 + c0] = aA1;
        *(uint2*)&g_hwh[base + c0]      = pack_half4(aA0);
        *(uint2*)&g_hwh[base + 32 + c0] = pack_half4(aA1);
    }
    if (r0 + 1 < n) {
        size_t base = (size_t)(r0 + 1) * 64;
        *(float4*)&g_hw[base + c0]      = aB0;
        *(float4*)&g_hw[base + 32 + c0] = aB1;
        *(uint2*)&g_hwh[base + c0]      = pack_half4(aB0);
        *(uint2*)&g_hwh[base + 32 + c0] = pack_half4(aB1);
    }
}

// ---------------------------------------------------------------------------
// Edge scatter: acc[row] += norm * hwh[col]  (fp16 gather, fp32 vector red)
#define EPB 64
__global__ void k_scatter(const int* __restrict__ rowp, const int* __restrict__ colp,
                          const float* __restrict__ attr, int which, int e) {
    __shared__ int   s_row[EPB];
    __shared__ int   s_col[EPB];
    __shared__ float s_nrm[EPB];
    float* acc = which ? g_acc2 : g_acc1;
    int tid = threadIdx.x;
    int base = blockIdx.x * EPB;
    if (tid < EPB) {
        int ei = base + tid;
        if (ei < e) {
            int r = rowp[ei], c = colp[ei];
            s_row[tid] = r;
            s_col[tid] = c;
            s_nrm[tid] = g_deg[r] * attr[ei] * g_deg[c];
        } else {
            s_row[tid] = -1;
        }
    }
    __syncthreads();
    int g = tid >> 4, t = tid & 15;
#pragma unroll
    for (int it = 0; it < 4; it++) {
        int li = g + it * 16;
        int r = s_row[li];
        if (r < 0) continue;
        float nrm = s_nrm[li];
        uint2 hv = *(const uint2*)&g_hwh[(size_t)s_col[li] * 64 + t * 4];
        __half2 h0 = *(__half2*)&hv.x;
        __half2 h1 = *(__half2*)&hv.y;
        float2 f0 = __half22float2(h0);
        float2 f1 = __half22float2(h1);
        float* dst = &acc[(size_t)r * 64 + t * 4];
        asm volatile("red.global.add.v4.f32 [%0], {%1,%2,%3,%4};"
                     :: "l"(dst), "f"(f0.x * nrm), "f"(f0.y * nrm),
                        "f"(f1.x * nrm), "f"(f1.y * nrm)
                     : "memory");
    }
}

// ---------------------------------------------------------------------------
// layer-1 epilogue: h1 = relu(acc1 + dinv^2 * hw + b1)   (self-loop in fp32)
__global__ void k_post1(const float* __restrict__ bias, int n) {
    int idx = blockIdx.x * blockDim.x + threadIdx.x;  // one float4 per thread
    if (idx >= n * 16) return;
    int i = idx >> 4, q = idx & 15;
    float d = g_deg[i];
    float sl = d * d;
    float4 a  = *(const float4*)&g_acc1[(size_t)idx * 4];
    float4 hv = *(const float4*)&g_hw [(size_t)idx * 4];
    float4 b  = *(const float4*)&bias[q * 4];
    float4 r;
    r.x = fmaxf(a.x + sl * hv.x + b.x, 0.f);
    r.y = fmaxf(a.y + sl * hv.y + b.y, 0.f);
    r.z = fmaxf(a.z + sl * hv.z + b.z, 0.f);
    r.w = fmaxf(a.w + sl * hv.w + b.w, 0.f);
    *(float4*)&g_h1[(size_t)idx * 4] = r;
}

// layer-2 epilogue fused with mean-pool accumulation
__global__ void k_post2_pool(const float* __restrict__ bias, int n) {
    __shared__ float4 sbuf[256];
    int tid = threadIdx.x;
    int q = tid & 15, r = tid >> 4;
    float4 b = *(const float4*)&bias[q * 4];
    float4 sum = make_float4(0.f, 0.f, 0.f, 0.f);
    int base = blockIdx.x * 1024;
#pragma unroll 4
    for (int it = 0; it < 64; it++) {
        int i = base + r + (it << 4);
        if (i >= n) break;
        float d = g_deg[i];
        float sl = d * d;
        const float4 a  = *(const float4*)&g_acc2[(size_t)i * 64 + q * 4];
        const float4 hv = *(const float4*)&g_hw [(size_t)i * 64 + q * 4];
        sum.x += fmaxf(a.x + sl * hv.x + b.x, 0.f);
        sum.y += fmaxf(a.y + sl * hv.y + b.y, 0.f);
        sum.z += fmaxf(a.z + sl * hv.z + b.z, 0.f);
        sum.w += fmaxf(a.w + sl * hv.w + b.w, 0.f);
    }
    sbuf[tid] = sum;
    __syncthreads();
    if (r == 0) {
        float4 tot = sbuf[q];
#pragma unroll
        for (int j = 1; j < 16; j++) {
            float4 v = sbuf[q + 16 * j];
            tot.x += v.x; tot.y += v.y; tot.z += v.z; tot.w += v.w;
        }
        float* dst = &g_pool[q * 4];
        asm volatile("red.global.add.v4.f32 [%0], {%1,%2,%3,%4};"
                     :: "l"(dst), "f"(tot.x), "f"(tot.y), "f"(tot.z), "f"(tot.w)
                     : "memory");
    }
}

// ---------------------------------------------------------------------------
// head: z = [pool/n, h_other];  out = relu(z@Wc1+bc1) @ Wc2 + bc2
__global__ void k_head(const float* __restrict__ Wc1, const float* __restrict__ bc1,
                       const float* __restrict__ Wc2, const float* __restrict__ bc2,
                       const float* __restrict__ h_other, float* __restrict__ out, int n) {
    __shared__ float z[128];
    __shared__ float hid[64];
    int t = threadIdx.x;
    if (t < 64) {
        z[t]      = g_pool[t] / (float)n;
        z[64 + t] = h_other[t];
    }
    __syncthreads();
    if (t < 64) {
        float s = bc1[t];
#pragma unroll 8
        for (int i = 0; i < 128; i++) s += z[i] * Wc1[i * 64 + t];
        hid[t] = fmaxf(s, 0.f);
    }
    __syncthreads();
    if (t < 3) {
        float s = bc2[t];
#pragma unroll
        for (int j = 0; j < 64; j++) s += hid[j] * Wc2[j * 3 + t];
        out[t] = s;
    }
}

// ---------------------------------------------------------------------------
extern "C" void kernel_launch(void* const* d_in, const int* in_sizes, int n_in,
                              void* d_out, int out_size) {
    const float* x        = (const float*)d_in[0];
    const int*   eidx     = (const int*)  d_in[1];
    const float* eattr    = (const float*)d_in[2];
    // d_in[3] = batch (unused; single graph)
    const float* W1       = (const float*)d_in[4];
    const float* b1       = (const float*)d_in[5];
    const float* W2       = (const float*)d_in[6];
    const float* b2       = (const float*)d_in[7];
    const float* Wc1      = (const float*)d_in[8];
    const float* bc1      = (const float*)d_in[9];
    const float* Wc2      = (const float*)d_in[10];
    const float* bc2      = (const float*)d_in[11];
    const float* h_other  = (const float*)d_in[12];
    float* out = (float*)d_out;

    int n = in_sizes[0] / HD;      // nodes
    int e = in_sizes[2];           // edges
    const int* rowp = eidx;
    const int* colp = eidx + e;

    // 1) init scratch
    k_init<<<2048, 256>>>(n);
    // 2) degree + dinv
    k_deg<<<(e + 255) / 256, 256>>>(rowp, eattr, e);
    k_dinv<<<(n + 255) / 256, 256>>>(n);
    // 3) layer 1: gemm -> scatter -> relu
    k_gemm<<<(n + 63) / 64, 256>>>(x, W1, 0, n);
    k_scatter<<<(e + EPB - 1) / EPB, 256>>>(rowp, colp, eattr, 0, e);
    k_post1<<<(n * 16 + 255) / 256, 256>>>(b1, n);
    // 4) layer 2: gemm -> scatter -> relu + pool
    k_gemm<<<(n + 63) / 64, 256>>>(x, W2, 1, n);
    k_scatter<<<(e + EPB - 1) / EPB, 256>>>(rowp, colp, eattr, 1, e);
    k_post2_pool<<<(n + 1023) / 1024, 256>>>(b2, n);
    // 5) head
    k_head<<<1, 64>>>(Wc1, bc1, Wc2, bc2, h_other, out, n);
}

// round 7
// speedup vs baseline: 6.2194x; 1.3129x over previous
#include <cuda_runtime.h>
#include <cuda_fp16.h>

#define NMAX 100000
#define EMAX 1600000
#define HD 64

// Scratch (device globals — allocation-free per harness rules)
__device__ float  g_deg[NMAX];            // degree, then dinv (in place)
__device__ float  g_hw [NMAX * HD];       // h @ W (per layer, fp32)
__device__ __half g_hwh[NMAX * HD];       // h @ W (per layer, fp16 mirror for gather)
__device__ float  g_h1 [NMAX * HD];       // post-relu layer-1 output
__device__ float  g_pool[HD];             // feature sums for mean pool
// CSR build
__device__ int    g_cnt [NMAX];           // per-row edge count
__device__ int    g_cur [NMAX];           // fill cursor
__device__ int    g_start[NMAX + 1];      // row offsets
__device__ int    g_bsum[128];            // scan partials
__device__ int    g_boff[128];            // scan partial offsets
__device__ int2   g_edat[EMAX];           // (col, norm-bits) in row-grouped order

// ---------------------------------------------------------------------------
__global__ void k_prep(int n) {
    int i = blockIdx.x * blockDim.x + threadIdx.x;
    int stride = gridDim.x * blockDim.x;
    for (int j = i; j < n; j += stride) { g_cnt[j] = 0; g_cur[j] = 0; g_deg[j] = 1.0f; }
    if (i < HD) g_pool[i] = 0.f;
}

// deg[row] += attr ; cnt[row]++
__global__ void k_deg_hist(const int* __restrict__ rowp, const float* __restrict__ attr, int e) {
    int i = blockIdx.x * blockDim.x + threadIdx.x;
    if (i < e) {
        int r = rowp[i];
        atomicAdd(&g_deg[r], attr[i]);
        atomicAdd(&g_cnt[r], 1);
    }
}

__global__ void k_dinv(int n) {
    int i = blockIdx.x * blockDim.x + threadIdx.x;
    if (i < n) g_deg[i] = rsqrtf(g_deg[i]);
}

// ---------------------------------------------------------------------------
// exclusive scan of g_cnt[0..n) into g_start  (1024 elems per block)
__global__ void k_scan1(int n) {
    __shared__ int ts[256];
    int tid = threadIdx.x;
    int base = blockIdx.x * 1024 + tid * 4;
    int v[4]; int s = 0;
#pragma unroll
    for (int i = 0; i < 4; i++) {
        int idx = base + i;
        v[i] = (idx < n) ? g_cnt[idx] : 0;
        s += v[i];
    }
    ts[tid] = s;
    __syncthreads();
    for (int off = 1; off < 256; off <<= 1) {
        int y = (tid >= off) ? ts[tid - off] : 0;
        __syncthreads();
        ts[tid] += y;
        __syncthreads();
    }
    int run = ts[tid] - s;   // exclusive within block
#pragma unroll
    for (int i = 0; i < 4; i++) {
        int idx = base + i;
        if (idx < n) g_start[idx] = run;
        run += v[i];
    }
    if (tid == 255) g_bsum[blockIdx.x] = ts[255];
}

__global__ void k_scan2(int nb, int n, int e) {
    __shared__ int sb[128];
    int tid = threadIdx.x;
    int own = (tid < nb) ? g_bsum[tid] : 0;
    sb[tid] = own;
    __syncthreads();
    for (int off = 1; off < 128; off <<= 1) {
        int y = (tid >= off) ? sb[tid - off] : 0;
        __syncthreads();
        sb[tid] += y;
        __syncthreads();
    }
    if (tid < nb) g_boff[tid] = sb[tid] - own;
    if (tid == 0) g_start[n] = e;
}

__global__ void k_scan3(int n) {
    int i = blockIdx.x * blockDim.x + threadIdx.x;
    if (i < n) g_start[i] += g_boff[i >> 10];
}

// fill CSR: (col, norm) per edge, grouped by row
__global__ void k_fill(const int* __restrict__ rowp, const int* __restrict__ colp,
                       const float* __restrict__ attr, int e) {
    int i = blockIdx.x * blockDim.x + threadIdx.x;
    if (i < e) {
        int r = rowp[i], c = colp[i];
        int pos = g_start[r] + atomicAdd(&g_cur[r], 1);
        float nrm = g_deg[r] * attr[i] * g_deg[c];
        g_edat[pos] = make_int2(c, __float_as_int(nrm));
    }
}

// ---------------------------------------------------------------------------
__device__ __forceinline__ uint2 pack_half4(float4 v) {
    __half2 lo = __floats2half2_rn(v.x, v.y);
    __half2 hi = __floats2half2_rn(v.z, v.w);
    uint2 u;
    u.x = *(unsigned int*)&lo;
    u.y = *(unsigned int*)&hi;
    return u;
}

// GEMM v8: 256 threads, 128 rows/block, thread = 4 rows x 8 interleaved cols.
// Per k per warp: 2 LDS.128 + 4 broadcast vs 32 FFMA -> FFMA-bound.
__global__ void __launch_bounds__(256) k_gemm(const float* __restrict__ inp,
                                              const float* __restrict__ W,
                                              int use_h1, int n) {
    __shared__ float sW[64 * 64];
    __shared__ float sX[128 * 65];
    const float* in = use_h1 ? g_h1 : inp;
    int tid = threadIdx.x;
    for (int j = tid; j < 1024; j += 256)
        ((float4*)sW)[j] = ((const float4*)W)[j];

    int rowBase = blockIdx.x * 128;
    for (int j = tid; j < 2048; j += 256) {   // 128 rows x 16 float4
        int r  = j >> 4;
        int c4 = (j & 15) * 4;
        int gr = rowBase + r;
        float4 v = (gr < n) ? *(const float4*)(in + (size_t)gr * 64 + c4)
                            : make_float4(0.f, 0.f, 0.f, 0.f);
        float* dst = &sX[r * 65 + c4];
        dst[0] = v.x; dst[1] = v.y; dst[2] = v.z; dst[3] = v.w;
    }
    __syncthreads();

    int c0 = (tid & 7) * 4;
    int rr = (tid >> 3) * 4;
    int off0 = rr * 65, off1 = off0 + 65, off2 = off1 + 65, off3 = off2 + 65;

    float4 c00 = make_float4(0.f,0.f,0.f,0.f), c01 = c00;
    float4 c10 = c00, c11 = c00, c20 = c00, c21 = c00, c30 = c00, c31 = c00;

#pragma unroll 8
    for (int k = 0; k < 64; k++) {
        float a0 = sX[off0 + k], a1 = sX[off1 + k];
        float a2 = sX[off2 + k], a3 = sX[off3 + k];
        float4 w0 = *(const float4*)&sW[k * 64 + c0];
        float4 w1 = *(const float4*)&sW[k * 64 + 32 + c0];
        c00.x += a0*w0.x; c00.y += a0*w0.y; c00.z += a0*w0.z; c00.w += a0*w0.w;
        c01.x += a0*w1.x; c01.y += a0*w1.y; c01.z += a0*w1.z; c01.w += a0*w1.w;
        c10.x += a1*w0.x; c10.y += a1*w0.y; c10.z += a1*w0.z; c10.w += a1*w0.w;
        c11.x += a1*w1.x; c11.y += a1*w1.y; c11.z += a1*w1.z; c11.w += a1*w1.w;
        c20.x += a2*w0.x; c20.y += a2*w0.y; c20.z += a2*w0.z; c20.w += a2*w0.w;
        c21.x += a2*w1.x; c21.y += a2*w1.y; c21.z += a2*w1.z; c21.w += a2*w1.w;
        c30.x += a3*w0.x; c30.y += a3*w0.y; c30.z += a3*w0.z; c30.w += a3*w0.w;
        c31.x += a3*w1.x; c31.y += a3*w1.y; c31.z += a3*w1.z; c31.w += a3*w1.w;
    }

    int r0 = rowBase + rr;
    float4 lo[4] = {c00, c10, c20, c30};
    float4 hi[4] = {c01, c11, c21, c31};
#pragma unroll
    for (int i = 0; i < 4; i++) {
        if (r0 + i < n) {
            size_t base = (size_t)(r0 + i) * 64;
            *(float4*)&g_hw[base + c0]      = lo[i];
            *(float4*)&g_hw[base + 32 + c0] = hi[i];
            *(uint2*)&g_hwh[base + c0]      = pack_half4(lo[i]);
            *(uint2*)&g_hwh[base + 32 + c0] = pack_half4(hi[i]);
        }
    }
}

// ---------------------------------------------------------------------------
// Aggregation: warp per node. acc = sum_j norm_j * hwh[col_j] (fp16 gather,
// fp32 accum) + dinv^2 * hw[node] + bias, relu.
// layer1: write g_h1. layer2: block-reduce into g_pool (no per-node output).
__global__ void __launch_bounds__(256) k_agg(const float* __restrict__ bias,
                                             int layer2, int n) {
    int lane = threadIdx.x & 31;
    int wid  = threadIdx.x >> 5;
    int node = blockIdx.x * 8 + wid;
    const __half2* hwh2 = (const __half2*)g_hwh;

    float2 acc = make_float2(0.f, 0.f);
    if (node < n) {
        int s   = g_start[node];
        int end = g_start[node + 1];
        int j = s;
        for (; j + 4 <= end; j += 4) {
            int2 e0 = g_edat[j],     e1 = g_edat[j + 1];
            int2 e2 = g_edat[j + 2], e3 = g_edat[j + 3];
            float2 f0 = __half22float2(hwh2[(size_t)e0.x * 32 + lane]);
            float2 f1 = __half22float2(hwh2[(size_t)e1.x * 32 + lane]);
            float2 f2 = __half22float2(hwh2[(size_t)e2.x * 32 + lane]);
            float2 f3 = __half22float2(hwh2[(size_t)e3.x * 32 + lane]);
            float n0 = __int_as_float(e0.y), n1 = __int_as_float(e1.y);
            float n2 = __int_as_float(e2.y), n3 = __int_as_float(e3.y);
            acc.x += n0 * f0.x + n1 * f1.x + n2 * f2.x + n3 * f3.x;
            acc.y += n0 * f0.y + n1 * f1.y + n2 * f2.y + n3 * f3.y;
        }
        for (; j < end; j++) {
            int2 ed = g_edat[j];
            float2 f = __half22float2(hwh2[(size_t)ed.x * 32 + lane]);
            float nm = __int_as_float(ed.y);
            acc.x += nm * f.x;
            acc.y += nm * f.y;
        }
        float d  = g_deg[node];
        float sl = d * d;
        float2 hw = *(const float2*)&g_hw[(size_t)node * 64 + lane * 2];
        float2 b  = *(const float2*)&bias[lane * 2];
        acc.x = fmaxf(acc.x + sl * hw.x + b.x, 0.f);
        acc.y = fmaxf(acc.y + sl * hw.y + b.y, 0.f);
        if (!layer2) *(float2*)&g_h1[(size_t)node * 64 + lane * 2] = acc;
    }

    if (layer2) {
        __shared__ float2 sred[256];
        sred[threadIdx.x] = acc;
        __syncthreads();
        if (wid == 0) {
            float2 t = sred[lane];
#pragma unroll
            for (int w = 1; w < 8; w++) {
                float2 v = sred[w * 32 + lane];
                t.x += v.x; t.y += v.y;
            }
            float* dst = &g_pool[lane * 2];
            asm volatile("red.global.add.v2.f32 [%0], {%1,%2};"
                         :: "l"(dst), "f"(t.x), "f"(t.y) : "memory");
        }
    }
}

// ---------------------------------------------------------------------------
// head: z = [pool/n, h_other];  out = relu(z@Wc1+bc1) @ Wc2 + bc2
__global__ void k_head(const float* __restrict__ Wc1, const float* __restrict__ bc1,
                       const float* __restrict__ Wc2, const float* __restrict__ bc2,
                       const float* __restrict__ h_other, float* __restrict__ out, int n) {
    __shared__ float z[128];
    __shared__ float hid[64];
    int t = threadIdx.x;
    if (t < 64) {
        z[t]      = g_pool[t] / (float)n;
        z[64 + t] = h_other[t];
    }
    __syncthreads();
    if (t < 64) {
        float s = bc1[t];
#pragma unroll 8
        for (int i = 0; i < 128; i++) s += z[i] * Wc1[i * 64 + t];
        hid[t] = fmaxf(s, 0.f);
    }
    __syncthreads();
    if (t < 3) {
        float s = bc2[t];
#pragma unroll
        for (int j = 0; j < 64; j++) s += hid[j] * Wc2[j * 3 + t];
        out[t] = s;
    }
}

// ---------------------------------------------------------------------------
extern "C" void kernel_launch(void* const* d_in, const int* in_sizes, int n_in,
                              void* d_out, int out_size) {
    const float* x        = (const float*)d_in[0];
    const int*   eidx     = (const int*)  d_in[1];
    const float* eattr    = (const float*)d_in[2];
    // d_in[3] = batch (unused; single graph)
    const float* W1       = (const float*)d_in[4];
    const float* b1       = (const float*)d_in[5];
    const float* W2       = (const float*)d_in[6];
    const float* b2       = (const float*)d_in[7];
    const float* Wc1      = (const float*)d_in[8];
    const float* bc1      = (const float*)d_in[9];
    const float* Wc2      = (const float*)d_in[10];
    const float* bc2      = (const float*)d_in[11];
    const float* h_other  = (const float*)d_in[12];
    float* out = (float*)d_out;

    int n = in_sizes[0] / HD;      // nodes
    int e = in_sizes[2];           // edges
    const int* rowp = eidx;
    const int* colp = eidx + e;
    int nb = (n + 1023) / 1024;    // scan blocks (<=128)

    // CSR build
    k_prep<<<512, 256>>>(n);
    k_deg_hist<<<(e + 255) / 256, 256>>>(rowp, eattr, e);
    k_dinv<<<(n + 255) / 256, 256>>>(n);
    k_scan1<<<nb, 256>>>(n);
    k_scan2<<<1, 128>>>(nb, n, e);
    k_scan3<<<(n + 255) / 256, 256>>>(n);
    k_fill<<<(e + 255) / 256, 256>>>(rowp, colp, eattr, e);
    // layer 1
    k_gemm<<<(n + 127) / 128, 256>>>(x, W1, 0, n);
    k_agg<<<(n + 7) / 8, 256>>>(b1, 0, n);
    // layer 2 (+ pool)
    k_gemm<<<(n + 127) / 128, 256>>>(x, W2, 1, n);
    k_agg<<<(n + 7) / 8, 256>>>(b2, 1, n);
    // head
    k_head<<<1, 64>>>(Wc1, bc1, Wc2, bc2, h_other, out, n);
}

// round 8
// speedup vs baseline: 6.6236x; 1.0650x over previous
#include <cuda_runtime.h>
#include <cuda_fp16.h>

#define NMAX 100000
#define EMAX 1600000
#define HD 64

// Scratch (device globals — allocation-free per harness rules)
__device__ float  g_deg[NMAX];            // degree, then dinv (in place)
__device__ __half g_hwh[NMAX * HD];       // h @ W (per layer, fp16)
__device__ __half g_h1 [NMAX * HD];       // post-relu layer-1 output (fp16)
__device__ float  g_pool[HD];             // feature sums for mean pool
// CSR build
__device__ int    g_cnt [NMAX];           // per-row edge count
__device__ int    g_cur [NMAX];           // fill cursor
__device__ int    g_start[NMAX + 1];      // row offsets
__device__ int    g_bsum[128];            // scan partials
__device__ int    g_boff[128];            // scan partial offsets
__device__ int2   g_edat[EMAX];           // (col, norm-bits) in row-grouped order

// ---------------------------------------------------------------------------
__global__ void k_prep(int n) {
    int i = blockIdx.x * blockDim.x + threadIdx.x;
    int stride = gridDim.x * blockDim.x;
    for (int j = i; j < n; j += stride) { g_cnt[j] = 0; g_cur[j] = 0; g_deg[j] = 1.0f; }
    if (i < HD) g_pool[i] = 0.f;
}

// deg[row] += attr ; cnt[row]++
__global__ void k_deg_hist(const int* __restrict__ rowp, const float* __restrict__ attr, int e) {
    int i = blockIdx.x * blockDim.x + threadIdx.x;
    if (i < e) {
        int r = rowp[i];
        atomicAdd(&g_deg[r], attr[i]);
        atomicAdd(&g_cnt[r], 1);
    }
}

// ---------------------------------------------------------------------------
// exclusive scan of g_cnt[0..n) into g_start (1024/block); also deg -> rsqrt(deg)
__global__ void k_scan1(int n) {
    __shared__ int ts[256];
    int tid = threadIdx.x;
    int base = blockIdx.x * 1024 + tid * 4;
    int v[4]; int s = 0;
#pragma unroll
    for (int i = 0; i < 4; i++) {
        int idx = base + i;
        v[i] = (idx < n) ? g_cnt[idx] : 0;
        s += v[i];
        if (idx < n) g_deg[idx] = rsqrtf(g_deg[idx]);   // fused dinv
    }
    ts[tid] = s;
    __syncthreads();
    for (int off = 1; off < 256; off <<= 1) {
        int y = (tid >= off) ? ts[tid - off] : 0;
        __syncthreads();
        ts[tid] += y;
        __syncthreads();
    }
    int run = ts[tid] - s;   // exclusive within block
#pragma unroll
    for (int i = 0; i < 4; i++) {
        int idx = base + i;
        if (idx < n) g_start[idx] = run;
        run += v[i];
    }
    if (tid == 255) g_bsum[blockIdx.x] = ts[255];
}

__global__ void k_scan2(int nb, int n, int e) {
    __shared__ int sb[128];
    int tid = threadIdx.x;
    int own = (tid < nb) ? g_bsum[tid] : 0;
    sb[tid] = own;
    __syncthreads();
    for (int off = 1; off < 128; off <<= 1) {
        int y = (tid >= off) ? sb[tid - off] : 0;
        __syncthreads();
        sb[tid] += y;
        __syncthreads();
    }
    if (tid < nb) g_boff[tid] = sb[tid] - own;
    if (tid == 0) g_start[n] = e;
}

__global__ void k_scan3(int n) {
    int i = blockIdx.x * blockDim.x + threadIdx.x;
    if (i < n) g_start[i] += g_boff[i >> 10];
}

// fill CSR: (col, norm) per edge, grouped by row
__global__ void k_fill(const int* __restrict__ rowp, const int* __restrict__ colp,
                       const float* __restrict__ attr, int e) {
    int i = blockIdx.x * blockDim.x + threadIdx.x;
    if (i < e) {
        int r = rowp[i], c = colp[i];
        int pos = g_start[r] + atomicAdd(&g_cur[r], 1);
        float nrm = g_deg[r] * attr[i] * g_deg[c];
        g_edat[pos] = make_int2(c, __float_as_int(nrm));
    }
}

// ---------------------------------------------------------------------------
__device__ __forceinline__ uint2 pack_half4(float4 v) {
    __half2 lo = __floats2half2_rn(v.x, v.y);
    __half2 hi = __floats2half2_rn(v.z, v.w);
    uint2 u;
    u.x = *(unsigned int*)&lo;
    u.y = *(unsigned int*)&hi;
    return u;
}

// GEMM v9: out = in @ W -> g_hwh (fp16 only).
// 256 threads, 128 rows/block, thread = 4 rows x 8 interleaved cols.
// Layer1 input: fp32 x. Layer2 input: fp16 g_h1 (converted at staging).
__global__ void __launch_bounds__(256) k_gemm(const float* __restrict__ inp,
                                              const float* __restrict__ W,
                                              int use_h1, int n) {
    __shared__ float sW[64 * 64];
    __shared__ float sX[128 * 65];
    int tid = threadIdx.x;
    for (int j = tid; j < 1024; j += 256)
        ((float4*)sW)[j] = ((const float4*)W)[j];

    int rowBase = blockIdx.x * 128;
    for (int j = tid; j < 2048; j += 256) {   // 128 rows x 16 quads
        int r  = j >> 4;
        int c4 = (j & 15) * 4;
        int gr = rowBase + r;
        float4 v;
        if (gr >= n) {
            v = make_float4(0.f, 0.f, 0.f, 0.f);
        } else if (use_h1) {
            const __half2* p = (const __half2*)(g_h1 + (size_t)gr * 64 + c4);
            float2 f0 = __half22float2(p[0]);
            float2 f1 = __half22float2(p[1]);
            v = make_float4(f0.x, f0.y, f1.x, f1.y);
        } else {
            v = *(const float4*)(inp + (size_t)gr * 64 + c4);
        }
        float* dst = &sX[r * 65 + c4];
        dst[0] = v.x; dst[1] = v.y; dst[2] = v.z; dst[3] = v.w;
    }
    __syncthreads();

    int c0 = (tid & 7) * 4;
    int rr = (tid >> 3) * 4;
    int off0 = rr * 65, off1 = off0 + 65, off2 = off1 + 65, off3 = off2 + 65;

    float4 c00 = make_float4(0.f,0.f,0.f,0.f), c01 = c00;
    float4 c10 = c00, c11 = c00, c20 = c00, c21 = c00, c30 = c00, c31 = c00;

#pragma unroll 8
    for (int k = 0; k < 64; k++) {
        float a0 = sX[off0 + k], a1 = sX[off1 + k];
        float a2 = sX[off2 + k], a3 = sX[off3 + k];
        float4 w0 = *(const float4*)&sW[k * 64 + c0];
        float4 w1 = *(const float4*)&sW[k * 64 + 32 + c0];
        c00.x += a0*w0.x; c00.y += a0*w0.y; c00.z += a0*w0.z; c00.w += a0*w0.w;
        c01.x += a0*w1.x; c01.y += a0*w1.y; c01.z += a0*w1.z; c01.w += a0*w1.w;
        c10.x += a1*w0.x; c10.y += a1*w0.y; c10.z += a1*w0.z; c10.w += a1*w0.w;
        c11.x += a1*w1.x; c11.y += a1*w1.y; c11.z += a1*w1.z; c11.w += a1*w1.w;
        c20.x += a2*w0.x; c20.y += a2*w0.y; c20.z += a2*w0.z; c20.w += a2*w0.w;
        c21.x += a2*w1.x; c21.y += a2*w1.y; c21.z += a2*w1.z; c21.w += a2*w1.w;
        c30.x += a3*w0.x; c30.y += a3*w0.y; c30.z += a3*w0.z; c30.w += a3*w0.w;
        c31.x += a3*w1.x; c31.y += a3*w1.y; c31.z += a3*w1.z; c31.w += a3*w1.w;
    }

    int r0 = rowBase + rr;
    float4 lo[4] = {c00, c10, c20, c30};
    float4 hi[4] = {c01, c11, c21, c31};
#pragma unroll
    for (int i = 0; i < 4; i++) {
        if (r0 + i < n) {
            size_t base = (size_t)(r0 + i) * 64;
            *(uint2*)&g_hwh[base + c0]      = pack_half4(lo[i]);
            *(uint2*)&g_hwh[base + 32 + c0] = pack_half4(hi[i]);
        }
    }
}

// ---------------------------------------------------------------------------
// Aggregation: warp per node. acc = sum_j norm_j * hwh[col_j] + dinv^2 *
// hwh[node] + bias, relu. layer1: write g_h1 (fp16). layer2: block-reduce pool.
__global__ void __launch_bounds__(256) k_agg(const float* __restrict__ bias,
                                             int layer2, int n) {
    int lane = threadIdx.x & 31;
    int wid  = threadIdx.x >> 5;
    int node = blockIdx.x * 8 + wid;
    const __half2* hwh2 = (const __half2*)g_hwh;

    float2 acc = make_float2(0.f, 0.f);
    if (node < n) {
        int s   = g_start[node];
        int end = g_start[node + 1];
        int j = s;
        for (; j + 4 <= end; j += 4) {
            int2 e0 = g_edat[j],     e1 = g_edat[j + 1];
            int2 e2 = g_edat[j + 2], e3 = g_edat[j + 3];
            float2 f0 = __half22float2(hwh2[(size_t)e0.x * 32 + lane]);
            float2 f1 = __half22float2(hwh2[(size_t)e1.x * 32 + lane]);
            float2 f2 = __half22float2(hwh2[(size_t)e2.x * 32 + lane]);
            float2 f3 = __half22float2(hwh2[(size_t)e3.x * 32 + lane]);
            float n0 = __int_as_float(e0.y), n1 = __int_as_float(e1.y);
            float n2 = __int_as_float(e2.y), n3 = __int_as_float(e3.y);
            acc.x += n0 * f0.x + n1 * f1.x + n2 * f2.x + n3 * f3.x;
            acc.y += n0 * f0.y + n1 * f1.y + n2 * f2.y + n3 * f3.y;
        }
        for (; j < end; j++) {
            int2 ed = g_edat[j];
            float2 f = __half22float2(hwh2[(size_t)ed.x * 32 + lane]);
            float nm = __int_as_float(ed.y);
            acc.x += nm * f.x;
            acc.y += nm * f.y;
        }
        float d  = g_deg[node];
        float sl = d * d;
        float2 hw = __half22float2(hwh2[(size_t)node * 32 + lane]);
        float2 b  = *(const float2*)&bias[lane * 2];
        acc.x = fmaxf(acc.x + sl * hw.x + b.x, 0.f);
        acc.y = fmaxf(acc.y + sl * hw.y + b.y, 0.f);
        if (!layer2)
            *(__half2*)&g_h1[(size_t)node * 64 + lane * 2] = __floats2half2_rn(acc.x, acc.y);
    }

    if (layer2) {
        __shared__ float2 sred[256];
        sred[threadIdx.x] = acc;
        __syncthreads();
        if (wid == 0) {
            float2 t = sred[lane];
#pragma unroll
            for (int w = 1; w < 8; w++) {
                float2 v = sred[w * 32 + lane];
                t.x += v.x; t.y += v.y;
            }
            float* dst = &g_pool[lane * 2];
            asm volatile("red.global.add.v2.f32 [%0], {%1,%2};"
                         :: "l"(dst), "f"(t.x), "f"(t.y) : "memory");
        }
    }
}

// ---------------------------------------------------------------------------
// head: z = [pool/n, h_other];  out = relu(z@Wc1+bc1) @ Wc2 + bc2
__global__ void k_head(const float* __restrict__ Wc1, const float* __restrict__ bc1,
                       const float* __restrict__ Wc2, const float* __restrict__ bc2,
                       const float* __restrict__ h_other, float* __restrict__ out, int n) {
    __shared__ float z[128];
    __shared__ float hid[64];
    int t = threadIdx.x;
    if (t < 64) {
        z[t]      = g_pool[t] / (float)n;
        z[64 + t] = h_other[t];
    }
    __syncthreads();
    if (t < 64) {
        float s = bc1[t];
#pragma unroll 8
        for (int i = 0; i < 128; i++) s += z[i] * Wc1[i * 64 + t];
        hid[t] = fmaxf(s, 0.f);
    }
    __syncthreads();
    if (t < 3) {
        float s = bc2[t];
#pragma unroll
        for (int j = 0; j < 64; j++) s += hid[j] * Wc2[j * 3 + t];
        out[t] = s;
    }
}

// ---------------------------------------------------------------------------
extern "C" void kernel_launch(void* const* d_in, const int* in_sizes, int n_in,
                              void* d_out, int out_size) {
    const float* x        = (const float*)d_in[0];
    const int*   eidx     = (const int*)  d_in[1];
    const float* eattr    = (const float*)d_in[2];
    // d_in[3] = batch (unused; single graph)
    const float* W1       = (const float*)d_in[4];
    const float* b1       = (const float*)d_in[5];
    const float* W2       = (const float*)d_in[6];
    const float* b2       = (const float*)d_in[7];
    const float* Wc1      = (const float*)d_in[8];
    const float* bc1      = (const float*)d_in[9];
    const float* Wc2      = (const float*)d_in[10];
    const float* bc2      = (const float*)d_in[11];
    const float* h_other  = (const float*)d_in[12];
    float* out = (float*)d_out;

    int n = in_sizes[0] / HD;      // nodes
    int e = in_sizes[2];           // edges
    const int* rowp = eidx;
    const int* colp = eidx + e;
    int nb = (n + 1023) / 1024;    // scan blocks (<=128)

    // CSR build
    k_prep<<<400, 256>>>(n);
    k_deg_hist<<<(e + 255) / 256, 256>>>(rowp, eattr, e);
    k_scan1<<<nb, 256>>>(n);              // scan + fused dinv
    k_scan2<<<1, 128>>>(nb, n, e);
    k_scan3<<<(n + 255) / 256, 256>>>(n);
    k_fill<<<(e + 255) / 256, 256>>>(rowp, colp, eattr, e);
    // layer 1
    k_gemm<<<(n + 127) / 128, 256>>>(x, W1, 0, n);
    k_agg<<<(n + 7) / 8, 256>>>(b1, 0, n);
    // layer 2 (+ pool)
    k_gemm<<<(n + 127) / 128, 256>>>(x, W2, 1, n);
    k_agg<<<(n + 7) / 8, 256>>>(b2, 1, n);
    // head
    k_head<<<1, 64>>>(Wc1, bc1, Wc2, bc2, h_other, out, n);
}

// round 11
// speedup vs baseline: 7.5035x; 1.1328x over previous
#include <cuda_runtime.h>
#include <cuda_fp16.h>
#include <mma.h>

using namespace nvcuda;

#define NMAX 100000
#define EMAX 1600000
#define HD 64

// Scratch (device globals — allocation-free per harness rules)
__device__ float  g_deg[NMAX];            // degree, then dinv (in place)
__device__ __half g_hwh[NMAX * HD];       // h @ W (per layer, fp16)
__device__ __half g_h1 [NMAX * HD];       // post-relu layer-1 output (fp16)
__device__ float  g_pool[HD];             // feature sums for mean pool
// CSR build
__device__ int    g_cnt [NMAX];           // per-row edge count
__device__ int    g_cur [NMAX];           // fill cursor
__device__ int    g_start[NMAX + 1];      // row offsets
__device__ int    g_bsum[128];            // scan partials
__device__ int    g_boff[128];            // scan partial offsets
__device__ int2   g_edat[EMAX];           // (col, norm-bits) in row-grouped order

// ---------------------------------------------------------------------------
__global__ void k_prep(int n) {
    int i = blockIdx.x * blockDim.x + threadIdx.x;
    int stride = gridDim.x * blockDim.x;
    for (int j = i; j < n; j += stride) { g_cnt[j] = 0; g_cur[j] = 0; g_deg[j] = 1.0f; }
    if (i < HD) g_pool[i] = 0.f;
}

// deg[row] += attr ; cnt[row]++
__global__ void k_deg_hist(const int* __restrict__ rowp, const float* __restrict__ attr, int e) {
    int i = blockIdx.x * blockDim.x + threadIdx.x;
    if (i < e) {
        int r = rowp[i];
        atomicAdd(&g_deg[r], attr[i]);
        atomicAdd(&g_cnt[r], 1);
    }
}

// ---------------------------------------------------------------------------
// exclusive scan of g_cnt[0..n) into g_start (1024/block); also deg -> rsqrt(deg)
__global__ void k_scan1(int n) {
    __shared__ int ts[256];
    int tid = threadIdx.x;
    int base = blockIdx.x * 1024 + tid * 4;
    int v[4]; int s = 0;
#pragma unroll
    for (int i = 0; i < 4; i++) {
        int idx = base + i;
        v[i] = (idx < n) ? g_cnt[idx] : 0;
        s += v[i];
        if (idx < n) g_deg[idx] = rsqrtf(g_deg[idx]);   // fused dinv
    }
    ts[tid] = s;
    __syncthreads();
    for (int off = 1; off < 256; off <<= 1) {
        int y = (tid >= off) ? ts[tid - off] : 0;
        __syncthreads();
        ts[tid] += y;
        __syncthreads();
    }
    int run = ts[tid] - s;   // exclusive within block
#pragma unroll
    for (int i = 0; i < 4; i++) {
        int idx = base + i;
        if (idx < n) g_start[idx] = run;
        run += v[i];
    }
    if (tid == 255) g_bsum[blockIdx.x] = ts[255];
}

// single-warp shfl scan of the <=128 block partials
__global__ void k_scan2(int nb, int n, int e) {
    int lane = threadIdx.x;
    int v[4]; int s = 0;
#pragma unroll
    for (int i = 0; i < 4; i++) {
        int idx = lane * 4 + i;
        v[i] = (idx < nb) ? g_bsum[idx] : 0;
        s += v[i];
    }
    int inc = s;
#pragma unroll
    for (int off = 1; off < 32; off <<= 1) {
        int y = __shfl_up_sync(0xFFFFFFFFu, inc, off);
        if (lane >= off) inc += y;
    }
    int run = inc - s;
#pragma unroll
    for (int i = 0; i < 4; i++) {
        int idx = lane * 4 + i;
        if (idx < nb) g_boff[idx] = run;
        run += v[i];
    }
    if (lane == 0) g_start[n] = e;
}

__global__ void k_scan3(int n) {
    int i = blockIdx.x * blockDim.x + threadIdx.x;
    if (i < n) g_start[i] += g_boff[i >> 10];
}

// fill CSR: (col, norm) per edge, grouped by row
__global__ void k_fill(const int* __restrict__ rowp, const int* __restrict__ colp,
                       const float* __restrict__ attr, int e) {
    int i = blockIdx.x * blockDim.x + threadIdx.x;
    if (i < e) {
        int r = rowp[i], c = colp[i];
        int pos = g_start[r] + atomicAdd(&g_cur[r], 1);
        float nrm = g_deg[r] * attr[i] * g_deg[c];
        g_edat[pos] = make_int2(c, __float_as_int(nrm));
    }
}

// ---------------------------------------------------------------------------
// GEMM v12 (tensor core): g_hwh = in @ W (fp16 in, fp32 acc, fp16 out).
// 256 threads = 8 warps; 128 rows/block; warp = 16 rows x 64 cols
// (4 acc fragments), K = 4 steps of 16.
// XLD = 80 halves (160 B): every wmma fragment pointer is 32-byte aligned.
// R10 bug fixed here: fp16 staging now loads uint4 (8 halves) per 8-half
// chunk — uint2 only covered half of each g_h1 row.
#define XLD 80
__global__ void __launch_bounds__(256) k_gemm(const float* __restrict__ inp,
                                              const float* __restrict__ W,
                                              int use_h1, int n) {
    __shared__ __align__(32) __half sW[64 * XLD];
    __shared__ __align__(32) __half sX[128 * XLD];
    __shared__ __align__(16) float  sOut[8][16 * 16];
    int tid = threadIdx.x;
    int wid = tid >> 5, lane = tid & 31;

    // stage W (fp32 -> fp16), 64x64
    for (int j = tid; j < 1024; j += 256) {
        int r = j >> 4, c4 = (j & 15) * 4;
        float4 v = *(const float4*)(W + r * 64 + c4);
        __half2* d = (__half2*)&sW[r * XLD + c4];
        d[0] = __floats2half2_rn(v.x, v.y);
        d[1] = __floats2half2_rn(v.z, v.w);
    }
    int rowBase = blockIdx.x * 128;
    if (use_h1) {
        // fp16 rows: 128 rows x 8 chunks of 8 halves (16 B each)
        for (int j = tid; j < 1024; j += 256) {
            int r = j >> 3, c8 = (j & 7) * 8;
            int gr = rowBase + r;
            uint4 v = (gr < n) ? *(const uint4*)(g_h1 + (size_t)gr * 64 + c8)
                               : make_uint4(0u, 0u, 0u, 0u);
            *(uint4*)&sX[r * XLD + c8] = v;
        }
    } else {
        for (int j = tid; j < 2048; j += 256) {
            int r = j >> 4, c4 = (j & 15) * 4;
            int gr = rowBase + r;
            float4 v = (gr < n) ? *(const float4*)(inp + (size_t)gr * 64 + c4)
                                : make_float4(0.f, 0.f, 0.f, 0.f);
            __half2* d = (__half2*)&sX[r * XLD + c4];
            d[0] = __floats2half2_rn(v.x, v.y);
            d[1] = __floats2half2_rn(v.z, v.w);
        }
    }
    __syncthreads();

    wmma::fragment<wmma::accumulator, 16, 16, 16, float> acc[4];
#pragma unroll
    for (int t = 0; t < 4; t++) wmma::fill_fragment(acc[t], 0.f);

#pragma unroll
    for (int kk = 0; kk < 4; kk++) {
        wmma::fragment<wmma::matrix_a, 16, 16, 16, __half, wmma::row_major> a;
        wmma::load_matrix_sync(a, &sX[(wid * 16) * XLD + kk * 16], XLD);
#pragma unroll
        for (int t = 0; t < 4; t++) {
            wmma::fragment<wmma::matrix_b, 16, 16, 16, __half, wmma::row_major> b;
            wmma::load_matrix_sync(b, &sW[(kk * 16) * XLD + t * 16], XLD);
            wmma::mma_sync(acc[t], a, b, acc[t]);
        }
    }

    // epilogue: per n-tile, roundtrip through smem, pack fp16, 16B stores
    int r0 = rowBase + wid * 16;
    int rr = lane >> 1, cc = (lane & 1) * 8;
#pragma unroll
    for (int t = 0; t < 4; t++) {
        wmma::store_matrix_sync(sOut[wid], acc[t], 16, wmma::mem_row_major);
        __syncwarp();
        if (r0 + rr < n) {
            const float* src = &sOut[wid][rr * 16 + cc];
            __half2 h0 = __floats2half2_rn(src[0], src[1]);
            __half2 h1 = __floats2half2_rn(src[2], src[3]);
            __half2 h2 = __floats2half2_rn(src[4], src[5]);
            __half2 h3 = __floats2half2_rn(src[6], src[7]);
            uint4 u;
            u.x = *(unsigned int*)&h0;
            u.y = *(unsigned int*)&h1;
            u.z = *(unsigned int*)&h2;
            u.w = *(unsigned int*)&h3;
            *(uint4*)&g_hwh[(size_t)(r0 + rr) * 64 + t * 16 + cc] = u;
        }
        __syncwarp();
    }
}

// ---------------------------------------------------------------------------
// Aggregation: warp per node. acc = sum_j norm_j * hwh[col_j] + dinv^2 *
// hwh[node] + bias, relu. layer1: write g_h1 (fp16). layer2: block-reduce pool.
__global__ void __launch_bounds__(256) k_agg(const float* __restrict__ bias,
                                             int layer2, int n) {
    int lane = threadIdx.x & 31;
    int wid  = threadIdx.x >> 5;
    int node = blockIdx.x * 8 + wid;
    const __half2* hwh2 = (const __half2*)g_hwh;

    float2 acc = make_float2(0.f, 0.f);
    if (node < n) {
        int s   = g_start[node];
        int end = g_start[node + 1];
        int j = s;
        for (; j + 4 <= end; j += 4) {
            int2 e0 = g_edat[j],     e1 = g_edat[j + 1];
            int2 e2 = g_edat[j + 2], e3 = g_edat[j + 3];
            float2 f0 = __half22float2(hwh2[(size_t)e0.x * 32 + lane]);
            float2 f1 = __half22float2(hwh2[(size_t)e1.x * 32 + lane]);
            float2 f2 = __half22float2(hwh2[(size_t)e2.x * 32 + lane]);
            float2 f3 = __half22float2(hwh2[(size_t)e3.x * 32 + lane]);
            float n0 = __int_as_float(e0.y), n1 = __int_as_float(e1.y);
            float n2 = __int_as_float(e2.y), n3 = __int_as_float(e3.y);
            acc.x += n0 * f0.x + n1 * f1.x + n2 * f2.x + n3 * f3.x;
            acc.y += n0 * f0.y + n1 * f1.y + n2 * f2.y + n3 * f3.y;
        }
        for (; j < end; j++) {
            int2 ed = g_edat[j];
            float2 f = __half22float2(hwh2[(size_t)ed.x * 32 + lane]);
            float nm = __int_as_float(ed.y);
            acc.x += nm * f.x;
            acc.y += nm * f.y;
        }
        float d  = g_deg[node];
        float sl = d * d;
        float2 hw = __half22float2(hwh2[(size_t)node * 32 + lane]);
        float2 b  = *(const float2*)&bias[lane * 2];
        acc.x = fmaxf(acc.x + sl * hw.x + b.x, 0.f);
        acc.y = fmaxf(acc.y + sl * hw.y + b.y, 0.f);
        if (!layer2)
            *(__half2*)&g_h1[(size_t)node * 64 + lane * 2] = __floats2half2_rn(acc.x, acc.y);
    }

    if (layer2) {
        __shared__ float2 sred[256];
        sred[threadIdx.x] = acc;
        __syncthreads();
        if (wid == 0) {
            float2 t = sred[lane];
#pragma unroll
            for (int w = 1; w < 8; w++) {
                float2 v = sred[w * 32 + lane];
                t.x += v.x; t.y += v.y;
            }
            float* dst = &g_pool[lane * 2];
            asm volatile("red.global.add.v2.f32 [%0], {%1,%2};"
                         :: "l"(dst), "f"(t.x), "f"(t.y) : "memory");
        }
    }
}

// ---------------------------------------------------------------------------
// head: z = [pool/n, h_other];  out = relu(z@Wc1+bc1) @ Wc2 + bc2
__global__ void k_head(const float* __restrict__ Wc1, const float* __restrict__ bc1,
                       const float* __restrict__ Wc2, const float* __restrict__ bc2,
                       const float* __restrict__ h_other, float* __restrict__ out, int n) {
    __shared__ float z[128];
    __shared__ float hid[64];
    int t = threadIdx.x;
    if (t < 64) {
        z[t]      = g_pool[t] / (float)n;
        z[64 + t] = h_other[t];
    }
    __syncthreads();
    if (t < 64) {
        float s = bc1[t];
#pragma unroll 8
        for (int i = 0; i < 128; i++) s += z[i] * Wc1[i * 64 + t];
        hid[t] = fmaxf(s, 0.f);
    }
    __syncthreads();
    if (t < 3) {
        float s = bc2[t];
#pragma unroll
        for (int j = 0; j < 64; j++) s += hid[j] * Wc2[j * 3 + t];
        out[t] = s;
    }
}

// ---------------------------------------------------------------------------
extern "C" void kernel_launch(void* const* d_in, const int* in_sizes, int n_in,
                              void* d_out, int out_size) {
    const float* x        = (const float*)d_in[0];
    const int*   eidx     = (const int*)  d_in[1];
    const float* eattr    = (const float*)d_in[2];
    // d_in[3] = batch (unused; single graph)
    const float* W1       = (const float*)d_in[4];
    const float* b1       = (const float*)d_in[5];
    const float* W2       = (const float*)d_in[6];
    const float* b2       = (const float*)d_in[7];
    const float* Wc1      = (const float*)d_in[8];
    const float* bc1      = (const float*)d_in[9];
    const float* Wc2      = (const float*)d_in[10];
    const float* bc2      = (const float*)d_in[11];
    const float* h_other  = (const float*)d_in[12];
    float* out = (float*)d_out;

    int n = in_sizes[0] / HD;      // nodes
    int e = in_sizes[2];           // edges
    const int* rowp = eidx;
    const int* colp = eidx + e;
    int nb = (n + 1023) / 1024;    // scan blocks (<=128)

    // CSR build
    k_prep<<<400, 256>>>(n);
    k_deg_hist<<<(e + 255) / 256, 256>>>(rowp, eattr, e);
    k_scan1<<<nb, 256>>>(n);              // scan + fused dinv
    k_scan2<<<1, 32>>>(nb, n, e);
    k_scan3<<<(n + 255) / 256, 256>>>(n);
    k_fill<<<(e + 255) / 256, 256>>>(rowp, colp, eattr, e);
    // layer 1
    k_gemm<<<(n + 127) / 128, 256>>>(x, W1, 0, n);
    k_agg<<<(n + 7) / 8, 256>>>(b1, 0, n);
    // layer 2 (+ pool)
    k_gemm<<<(n + 127) / 128, 256>>>(x, W2, 1, n);
    k_agg<<<(n + 7) / 8, 256>>>(b2, 1, n);
    // head
    k_head<<<1, 64>>>(Wc1, bc1, Wc2, bc2, h_other, out, n);
}